// round 11
// baseline (speedup 1.0000x reference)
#include <cuda_runtime.h>
#include <cuda_fp16.h>
#include <cstdint>

#define TEMPERATURE 0.07f
constexpr int BSZ  = 256;
constexpr int MTOK = 128;
constexpr int DDIM = 768;

constexpr int KC     = 96;                 // K elements per smem stage (fp16)
constexpr int NCHUNK = DDIM / KC;          // 8
constexpr int NSTEP  = KC / 16;            // 6 K16 steps per chunk
constexpr int PB     = 208;                // smem row pitch bytes (192 data + 16 pad)
constexpr int TILE_B = 128 * PB;           // 26624 bytes per tile
constexpr int STAGE_B = 2 * TILE_B;        // A, B
constexpr int SMEM_TOTAL = 2 * STAGE_B;    // 106496, double buffered -> occ 2

// Scratch device globals (no allocation allowed anywhere)
__device__ float g_S [BSZ * BSZ];          // max-sim, row-major
__device__ float g_ST[BSZ * BSZ];          // transposed copy (coalesced cols)
__device__ float g_partial[BSZ];
__device__ unsigned g_count;
__device__ __align__(16) __half g_Ah[BSZ * DDIM];

// ---------------------------------------------------------------------------
__device__ __forceinline__ uint32_t smem_u32(const void* p) {
    uint32_t a;
    asm("{ .reg .u64 t; cvta.to.shared.u64 t, %1; cvt.u32.u64 %0, t; }"
        : "=r"(a) : "l"(p));
    return a;
}
__device__ __forceinline__ void cp_async16(uint32_t dst, const void* src) {
    asm volatile("cp.async.cg.shared.global [%0], [%1], 16;"
                 :: "r"(dst), "l"(src) : "memory");
}
#define CP_COMMIT() asm volatile("cp.async.commit_group;" ::: "memory")
#define CP_WAIT0()  asm volatile("cp.async.wait_group 0;" ::: "memory")

__device__ __forceinline__ void ldsm_x4(uint32_t* r, uint32_t addr) {
    asm volatile("ldmatrix.sync.aligned.m8n8.x4.shared.b16 {%0,%1,%2,%3}, [%4];"
                 : "=r"(r[0]), "=r"(r[1]), "=r"(r[2]), "=r"(r[3]) : "r"(addr));
}
__device__ __forceinline__ void mma_fp16(float* d, const uint32_t* a,
                                         const uint32_t* b) {
    asm volatile(
        "mma.sync.aligned.m16n8k16.row.col.f32.f16.f16.f32 "
        "{%0,%1,%2,%3}, {%4,%5,%6,%7}, {%8,%9}, {%0,%1,%2,%3};"
        : "+f"(d[0]), "+f"(d[1]), "+f"(d[2]), "+f"(d[3])
        : "r"(a[0]), "r"(a[1]), "r"(a[2]), "r"(a[3]), "r"(b[0]), "r"(b[1]));
}

// ---------------------------------------------------------------------------
// Kernel 0: convert V (fp32) to fp16 once (float4-wide); reset counter.
// ---------------------------------------------------------------------------
__global__ void convert_a_kernel(const float* __restrict__ V) {
    int idx = blockIdx.x * blockDim.x + threadIdx.x;   // float4 index
    if (idx == 0) g_count = 0u;
    if (idx < BSZ * DDIM / 4) {
        const float4 x = *(const float4*)(V + (size_t)idx * 4);
        __half2 h01 = __floats2half2_rn(x.x, x.y);
        __half2 h23 = __floats2half2_rn(x.z, x.w);
        *(uint2*)(g_Ah + (size_t)idx * 4) =
            make_uint2(*reinterpret_cast<unsigned*>(&h01),
                       *reinterpret_cast<unsigned*>(&h23));
    }
}

// ---------------------------------------------------------------------------
// Kernel 1: single-product fp16 mma.sync GEMM + fused max over m.
// Grid (2, 256), 8 warps (4M x 2N), warp tile 32x64, occ 2, KC=96 (8 chunks).
// B prefetch split: part1 (k0-63) before compute, part2 (k64-95) after step 2
// (disjoint register live ranges keep pressure at ~br[8] level).
// ---------------------------------------------------------------------------
__global__ __launch_bounds__(256, 2)
void gemm_max_mma(const float* __restrict__ T) {
    extern __shared__ char smem[];
    const uint32_t sbase = smem_u32(smem);
    const int tid  = threadIdx.x;
    const int lane = tid & 31;
    const int wid  = tid >> 5;
    const int warp_m = wid & 3;
    const int warp_n = wid >> 2;

    const int i0 = blockIdx.x * 128;
    const int j  = blockIdx.y;
    const float* __restrict__ Tj = T + (size_t)j * MTOK * DDIM;

    float acc[2][8][4];
#pragma unroll
    for (int mt = 0; mt < 2; mt++)
#pragma unroll
        for (int nt = 0; nt < 8; nt++)
#pragma unroll
            for (int e = 0; e < 4; e++) acc[mt][nt][e] = 0.0f;

    // ldmatrix lane offsets (tile-relative, bytes)
    const int q   = lane >> 3;
    const int idx = lane & 7;
    const uint32_t a_off = (uint32_t)((warp_m * 32 + ((q & 1) * 8 + idx)) * PB
                                      + (q >> 1) * 16);
    const uint32_t b_off = (uint32_t)((warp_n * 64 + ((q >> 1) * 8 + idx)) * PB
                                      + (q & 1) * 16);

    float4 br[8];   // B part1 prefetch (k 0..63 of chunk)
    float4 b2[4];   // B part2 prefetch (k 64..95 of chunk)

    // A fill: cp.async, 6 x 16B per thread (128 rows x 12 16B-chunks).
    auto fill_A = [&](uint32_t stage_u32, int k0) {
#pragma unroll
        for (int p = 0; p < 6; p++) {
            const int u   = p * 256 + tid;   // 0..1535
            const int row = u / 12;
            const int ku  = u % 12;
            cp_async16(stage_u32 + (uint32_t)(row * PB + ku * 16),
                       g_Ah + (size_t)(i0 + row) * DDIM + k0 + ku * 8);
        }
    };
    auto ldg_B1 = [&](int k0) {
#pragma unroll
        for (int p = 0; p < 8; p++) {
            const int u = p * 256 + tid;     // row = u>>4, k-quad = u&15
            br[p] = *(const float4*)(Tj + (size_t)(u >> 4) * DDIM + k0 + (u & 15) * 4);
        }
    };
    auto ldg_B2 = [&](int k0) {
#pragma unroll
        for (int p = 0; p < 4; p++) {
            const int u = p * 256 + tid;     // row = u>>3, quad within k64..95
            b2[p] = *(const float4*)(Tj + (size_t)(u >> 3) * DDIM + k0 + 64 + (u & 7) * 4);
        }
    };
    auto sts_B1 = [&](char* stage) {
        char* sB = stage + TILE_B;
#pragma unroll
        for (int p = 0; p < 8; p++) {
            const int u   = p * 256 + tid;
            const int row = u >> 4;
            const int kq  = (u & 15) * 4;
            const float4 b = br[p];
            __half2 h01 = __floats2half2_rn(b.x, b.y);
            __half2 h23 = __floats2half2_rn(b.z, b.w);
            *(uint2*)(sB + row * PB + kq * 2) =
                make_uint2(*reinterpret_cast<unsigned*>(&h01),
                           *reinterpret_cast<unsigned*>(&h23));
        }
    };
    auto sts_B2 = [&](char* stage) {
        char* sB = stage + TILE_B;
#pragma unroll
        for (int p = 0; p < 4; p++) {
            const int u   = p * 256 + tid;
            const int row = u >> 3;
            const int kq  = 64 + (u & 7) * 4;
            const float4 b = b2[p];
            __half2 h01 = __floats2half2_rn(b.x, b.y);
            __half2 h23 = __floats2half2_rn(b.z, b.w);
            *(uint2*)(sB + row * PB + kq * 2) =
                make_uint2(*reinterpret_cast<unsigned*>(&h01),
                           *reinterpret_cast<unsigned*>(&h23));
        }
    };
    auto compute_step = [&](uint32_t sstage, int ks) {
        uint32_t ah[2][4], bh[4][4];
#pragma unroll
        for (int mt = 0; mt < 2; mt++)
            ldsm_x4(ah[mt], sstage + a_off + mt * 16 * PB + ks * 32);
#pragma unroll
        for (int np = 0; np < 4; np++)
            ldsm_x4(bh[np], sstage + TILE_B + b_off + np * 16 * PB + ks * 32);
#pragma unroll
        for (int np = 0; np < 4; np++)
#pragma unroll
            for (int mt = 0; mt < 2; mt++) {
                mma_fp16(acc[mt][2 * np],     ah[mt], bh[np]);
                mma_fp16(acc[mt][2 * np + 1], ah[mt], bh[np] + 2);
            }
    };

    // Prologue: chunk 0 -> stage 0.
    ldg_B1(0);
    fill_A(sbase, 0);
    CP_COMMIT();
    sts_B1(smem);
    ldg_B2(0);
    sts_B2(smem);
    CP_WAIT0();
    __syncthreads();

    for (int c = 0; c < NCHUNK; c++) {
        const int s = c & 1;
        const bool has_next = (c + 1 < NCHUNK);
        const int  knext = (c + 1) * KC;
        char* other = smem + (1 - s) * STAGE_B;
        if (has_next) {
            ldg_B1(knext);                                 // LDG latency hidden
            fill_A(sbase + (1 - s) * STAGE_B, knext);      // under MMA stream
            CP_COMMIT();
        }
        const uint32_t sstage = sbase + s * STAGE_B;
        compute_step(sstage, 0);
        compute_step(sstage, 1);
        compute_step(sstage, 2);
        if (has_next) { sts_B1(other); ldg_B2(knext); }    // part2 LDG ~2 steps early
        compute_step(sstage, 3);
        compute_step(sstage, 4);
        if (has_next) sts_B2(other);
        compute_step(sstage, 5);
        if (has_next) CP_WAIT0();
        __syncthreads();
    }

    // Epilogue: max over the 128 m columns per i-row; write S and S^T.
    float* buf = (float*)smem;   // [128][2]
#pragma unroll
    for (int mt = 0; mt < 2; mt++) {
        float mlo = -3.402823466e+38f, mhi = -3.402823466e+38f;
#pragma unroll
        for (int nt = 0; nt < 8; nt++) {
            mlo = fmaxf(mlo, fmaxf(acc[mt][nt][0], acc[mt][nt][1]));
            mhi = fmaxf(mhi, fmaxf(acc[mt][nt][2], acc[mt][nt][3]));
        }
        mlo = fmaxf(mlo, __shfl_xor_sync(0xffffffffu, mlo, 1));
        mlo = fmaxf(mlo, __shfl_xor_sync(0xffffffffu, mlo, 2));
        mhi = fmaxf(mhi, __shfl_xor_sync(0xffffffffu, mhi, 1));
        mhi = fmaxf(mhi, __shfl_xor_sync(0xffffffffu, mhi, 2));
        if ((lane & 3) == 0) {
            const int row = warp_m * 32 + mt * 16 + (lane >> 2);
            buf[row * 2 + warp_n]       = mlo;
            buf[(row + 8) * 2 + warp_n] = mhi;
        }
    }
    __syncthreads();
    if (tid < 128) {
        const float v = fmaxf(buf[tid * 2], buf[tid * 2 + 1]);
        g_S [(size_t)(i0 + tid) * BSZ + j]  = v;
        g_ST[(size_t)j * BSZ + (i0 + tid)]  = v;   // coalesced
    }
}

// ---------------------------------------------------------------------------
// Kernel 2: per-index LSE terms via shfl reductions (coalesced reads from
// g_S and g_ST); last block does the deterministic final sum + state reset.
// ---------------------------------------------------------------------------
__global__ void lse_finalize_kernel(float* __restrict__ out) {
    __shared__ float red[2][8];
    __shared__ float bsum[8];
    __shared__ unsigned is_last;
    const int i    = blockIdx.x;
    const int t    = threadIdx.x;
    const int lane = t & 31;
    const int w    = t >> 5;
    const float INV = 1.0f / TEMPERATURE;

    const float rv   = g_S [(size_t)i * BSZ + t] * INV;   // logit row i
    const float cv   = g_ST[(size_t)i * BSZ + t] * INV;   // logit col i
    const float diag = g_S[(size_t)i * BSZ + i] * INV;

    // ---- block max (warp shfl + 8-entry smem hop) ----
    float rm = rv, cm = cv;
#pragma unroll
    for (int s = 16; s >= 1; s >>= 1) {
        rm = fmaxf(rm, __shfl_xor_sync(0xffffffffu, rm, s));
        cm = fmaxf(cm, __shfl_xor_sync(0xffffffffu, cm, s));
    }
    if (lane == 0) { red[0][w] = rm; red[1][w] = cm; }
    __syncthreads();
#pragma unroll
    for (int k = 0; k < 8; k++) {
        rm = fmaxf(rm, red[0][k]);
        cm = fmaxf(cm, red[1][k]);
    }
    __syncthreads();   // before red reuse

    // ---- block sum of exp ----
    float re = expf(rv - rm), ce = expf(cv - cm);
#pragma unroll
    for (int s = 16; s >= 1; s >>= 1) {
        re += __shfl_xor_sync(0xffffffffu, re, s);
        ce += __shfl_xor_sync(0xffffffffu, ce, s);
    }
    if (lane == 0) { red[0][w] = re; red[1][w] = ce; }
    __syncthreads();

    if (t == 0) {
        float rs = 0.0f, cs = 0.0f;
#pragma unroll
        for (int k = 0; k < 8; k++) { rs += red[0][k]; cs += red[1][k]; }
        g_partial[i] = (rm + logf(rs) - diag) + (cm + logf(cs) - diag);
        __threadfence();
        unsigned done = atomicAdd(&g_count, 1u);
        is_last = (done == (unsigned)(BSZ - 1)) ? 1u : 0u;
    }
    __syncthreads();

    if (is_last) {
        __threadfence();                 // make all g_partial writes visible
        float v = g_partial[t];
#pragma unroll
        for (int s = 16; s >= 1; s >>= 1) v += __shfl_xor_sync(0xffffffffu, v, s);
        if (lane == 0) bsum[w] = v;
        __syncthreads();
        if (t == 0) {
            float tot = 0.0f;
#pragma unroll
            for (int k = 0; k < 8; k++) tot += bsum[k];
            out[0] = tot * (1.0f / (2.0f * (float)BSZ));
            g_count = 0u;               // reset for next graph replay
            __threadfence();
        }
    }
}

// ---------------------------------------------------------------------------
extern "C" void kernel_launch(void* const* d_in, const int* in_sizes, int n_in,
                              void* d_out, int out_size) {
    const float* V = (const float*)d_in[0];  // v_final [256, 768]
    const float* T = (const float*)d_in[1];  // T_fused [256, 128, 768]
    float* out = (float*)d_out;

    cudaFuncSetAttribute(gemm_max_mma, cudaFuncAttributeMaxDynamicSharedMemorySize,
                         SMEM_TOTAL);

    convert_a_kernel<<<(BSZ * DDIM / 4 + 255) / 256, 256>>>(V);
    gemm_max_mma<<<dim3(2, BSZ), 256, SMEM_TOTAL>>>(T);
    lse_finalize_kernel<<<BSZ, BSZ>>>(out);
}

// round 12
// speedup vs baseline: 1.0747x; 1.0747x over previous
#include <cuda_runtime.h>
#include <cuda_fp16.h>
#include <cstdint>

#define TEMPERATURE 0.07f
constexpr int BSZ  = 256;
constexpr int MTOK = 128;
constexpr int DDIM = 768;

constexpr int KC      = 64;                // K elements per smem stage (fp16)
constexpr int NCHUNK  = DDIM / KC;         // 12
constexpr int PB      = 144;               // smem row pitch bytes (128 data + 16 pad)
constexpr int TILE_A  = 64 * PB;           // 9216  (A: 64 rows)
constexpr int TILE_Bb = 128 * PB;          // 18432 (B: 128 m rows)
constexpr int STAGE_B = TILE_A + TILE_Bb;  // 27648
constexpr int SMEM_TOTAL = 2 * STAGE_B;    // 55296, double buffered -> occ 4

// Scratch device globals (no allocation allowed anywhere)
__device__ float g_S [BSZ * BSZ];          // max-sim, row-major
__device__ float g_ST[BSZ * BSZ];          // transposed copy (coalesced cols)
__device__ float g_partial[BSZ];
__device__ unsigned g_count;
__device__ __align__(16) __half g_Ah[BSZ * DDIM];

// ---------------------------------------------------------------------------
__device__ __forceinline__ uint32_t smem_u32(const void* p) {
    uint32_t a;
    asm("{ .reg .u64 t; cvta.to.shared.u64 t, %1; cvt.u32.u64 %0, t; }"
        : "=r"(a) : "l"(p));
    return a;
}
__device__ __forceinline__ void cp_async16(uint32_t dst, const void* src) {
    asm volatile("cp.async.cg.shared.global [%0], [%1], 16;"
                 :: "r"(dst), "l"(src) : "memory");
}
#define CP_COMMIT() asm volatile("cp.async.commit_group;" ::: "memory")
#define CP_WAIT0()  asm volatile("cp.async.wait_group 0;" ::: "memory")

__device__ __forceinline__ void ldsm_x4(uint32_t* r, uint32_t addr) {
    asm volatile("ldmatrix.sync.aligned.m8n8.x4.shared.b16 {%0,%1,%2,%3}, [%4];"
                 : "=r"(r[0]), "=r"(r[1]), "=r"(r[2]), "=r"(r[3]) : "r"(addr));
}
__device__ __forceinline__ void mma_fp16(float* d, const uint32_t* a,
                                         const uint32_t* b) {
    asm volatile(
        "mma.sync.aligned.m16n8k16.row.col.f32.f16.f16.f32 "
        "{%0,%1,%2,%3}, {%4,%5,%6,%7}, {%8,%9}, {%0,%1,%2,%3};"
        : "+f"(d[0]), "+f"(d[1]), "+f"(d[2]), "+f"(d[3])
        : "r"(a[0]), "r"(a[1]), "r"(a[2]), "r"(a[3]), "r"(b[0]), "r"(b[1]));
}

// ---------------------------------------------------------------------------
// Kernel 0: convert V (fp32) to fp16 once (float4-wide); reset counter.
// ---------------------------------------------------------------------------
__global__ void convert_a_kernel(const float* __restrict__ V) {
    int idx = blockIdx.x * blockDim.x + threadIdx.x;   // float4 index
    if (idx == 0) g_count = 0u;
    if (idx < BSZ * DDIM / 4) {
        const float4 x = *(const float4*)(V + (size_t)idx * 4);
        __half2 h01 = __floats2half2_rn(x.x, x.y);
        __half2 h23 = __floats2half2_rn(x.z, x.w);
        *(uint2*)(g_Ah + (size_t)idx * 4) =
            make_uint2(*reinterpret_cast<unsigned*>(&h01),
                       *reinterpret_cast<unsigned*>(&h23));
    }
}

// ---------------------------------------------------------------------------
// Kernel 1: single-product fp16 mma.sync GEMM + fused max over m.
// Tile M=64 x N=128 (fine-grained for load balance: 1024 tiles / 148 SMs).
// Grid (4, 256), 128 threads = 4 warps (2M x 2N), warp tile 32x64, occ 4.
// A via cp.async (pre-converted fp16). B via register prefetch split into
// K-halves (8 float4 live at a time, disjoint ranges — 128-reg budget).
// ---------------------------------------------------------------------------
__global__ __launch_bounds__(128, 4)
void gemm_max_mma(const float* __restrict__ T) {
    extern __shared__ char smem[];
    const uint32_t sbase = smem_u32(smem);
    const int tid  = threadIdx.x;
    const int lane = tid & 31;
    const int wid  = tid >> 5;
    const int warp_m = wid & 1;
    const int warp_n = wid >> 1;

    const int i0 = blockIdx.x * 64;
    const int j  = blockIdx.y;
    const float* __restrict__ Tj = T + (size_t)j * MTOK * DDIM;

    float acc[2][8][4];
#pragma unroll
    for (int mt = 0; mt < 2; mt++)
#pragma unroll
        for (int nt = 0; nt < 8; nt++)
#pragma unroll
            for (int e = 0; e < 4; e++) acc[mt][nt][e] = 0.0f;

    // ldmatrix lane offsets (tile-relative, bytes)
    const int q   = lane >> 3;
    const int idx = lane & 7;
    const uint32_t a_off = (uint32_t)((warp_m * 32 + ((q & 1) * 8 + idx)) * PB
                                      + (q >> 1) * 16);
    const uint32_t b_off = (uint32_t)((warp_n * 64 + ((q >> 1) * 8 + idx)) * PB
                                      + (q & 1) * 16);

    float4 br[8];   // B prefetch, one K-half at a time (disjoint live ranges)

    // A fill: cp.async, 4 x 16B per thread (64 rows x 8 16B-units).
    auto fill_A = [&](uint32_t stage_u32, int k0) {
#pragma unroll
        for (int p = 0; p < 4; p++) {
            const int u   = p * 128 + tid;   // 0..511
            const int row = u >> 3;
            const int ku  = u & 7;
            cp_async16(stage_u32 + (uint32_t)(row * PB + ku * 16),
                       g_Ah + (size_t)(i0 + row) * DDIM + k0 + ku * 8);
        }
    };
    // B LDG half: 8 float4 per thread covering 128 rows x 32 k.
    auto ldg_Bh = [&](int k0, int koff) {
#pragma unroll
        for (int p = 0; p < 8; p++) {
            const int u = p * 128 + tid;     // 0..1023: row = u>>3, quad = u&7
            br[p] = *(const float4*)(Tj + (size_t)(u >> 3) * DDIM + k0 + koff
                                     + (u & 7) * 4);
        }
    };
    auto sts_Bh = [&](char* stage, int koff) {
        char* sB = stage + TILE_A;
#pragma unroll
        for (int p = 0; p < 8; p++) {
            const int u   = p * 128 + tid;
            const int row = u >> 3;
            const int kq  = koff + (u & 7) * 4;
            const float4 b = br[p];
            __half2 h01 = __floats2half2_rn(b.x, b.y);
            __half2 h23 = __floats2half2_rn(b.z, b.w);
            *(uint2*)(sB + row * PB + kq * 2) =
                make_uint2(*reinterpret_cast<unsigned*>(&h01),
                           *reinterpret_cast<unsigned*>(&h23));
        }
    };
    auto compute_step = [&](uint32_t sstage, int ks) {
        uint32_t ah[2][4], bh[4][4];
#pragma unroll
        for (int mt = 0; mt < 2; mt++)
            ldsm_x4(ah[mt], sstage + a_off + mt * 16 * PB + ks * 32);
#pragma unroll
        for (int np = 0; np < 4; np++)
            ldsm_x4(bh[np], sstage + TILE_A + b_off + np * 16 * PB + ks * 32);
#pragma unroll
        for (int np = 0; np < 4; np++)
#pragma unroll
            for (int mt = 0; mt < 2; mt++) {
                mma_fp16(acc[mt][2 * np],     ah[mt], bh[np]);
                mma_fp16(acc[mt][2 * np + 1], ah[mt], bh[np] + 2);
            }
    };

    // Prologue: chunk 0 -> stage 0.
    ldg_Bh(0, 0);
    fill_A(sbase, 0);
    CP_COMMIT();
    sts_Bh(smem, 0);
    ldg_Bh(0, 32);
    sts_Bh(smem, 32);
    CP_WAIT0();
    __syncthreads();

    for (int c = 0; c < NCHUNK; c++) {
        const int s = c & 1;
        const bool has_next = (c + 1 < NCHUNK);
        const int  knext = (c + 1) * KC;
        char* other = smem + (1 - s) * STAGE_B;
        if (has_next) {
            ldg_Bh(knext, 0);                              // B half1 LDG ->
            fill_A(sbase + (1 - s) * STAGE_B, knext);      // latency hidden
            CP_COMMIT();                                   // under MMA stream
        }
        const uint32_t sstage = sbase + s * STAGE_B;
        compute_step(sstage, 0);
        compute_step(sstage, 1);
        if (has_next) { sts_Bh(other, 0); ldg_Bh(knext, 32); }
        compute_step(sstage, 2);
        if (has_next) sts_Bh(other, 32);
        compute_step(sstage, 3);
        if (has_next) CP_WAIT0();
        __syncthreads();
    }

    // Epilogue: max over the 128 m columns per i-row; write S and S^T.
    float* buf = (float*)smem;   // [64][2]
#pragma unroll
    for (int mt = 0; mt < 2; mt++) {
        float mlo = -3.402823466e+38f, mhi = -3.402823466e+38f;
#pragma unroll
        for (int nt = 0; nt < 8; nt++) {
            mlo = fmaxf(mlo, fmaxf(acc[mt][nt][0], acc[mt][nt][1]));
            mhi = fmaxf(mhi, fmaxf(acc[mt][nt][2], acc[mt][nt][3]));
        }
        mlo = fmaxf(mlo, __shfl_xor_sync(0xffffffffu, mlo, 1));
        mlo = fmaxf(mlo, __shfl_xor_sync(0xffffffffu, mlo, 2));
        mhi = fmaxf(mhi, __shfl_xor_sync(0xffffffffu, mhi, 1));
        mhi = fmaxf(mhi, __shfl_xor_sync(0xffffffffu, mhi, 2));
        if ((lane & 3) == 0) {
            const int row = warp_m * 32 + mt * 16 + (lane >> 2);
            buf[row * 2 + warp_n]       = mlo;
            buf[(row + 8) * 2 + warp_n] = mhi;
        }
    }
    __syncthreads();
    if (tid < 64) {
        const float v = fmaxf(buf[tid * 2], buf[tid * 2 + 1]);
        g_S [(size_t)(i0 + tid) * BSZ + j]  = v;
        g_ST[(size_t)j * BSZ + (i0 + tid)]  = v;   // coalesced
    }
}

// ---------------------------------------------------------------------------
// Kernel 2: per-index LSE terms via shfl reductions (coalesced reads from
// g_S and g_ST); last block does the deterministic final sum + state reset.
// ---------------------------------------------------------------------------
__global__ void lse_finalize_kernel(float* __restrict__ out) {
    __shared__ float red[2][8];
    __shared__ float bsum[8];
    __shared__ unsigned is_last;
    const int i    = blockIdx.x;
    const int t    = threadIdx.x;
    const int lane = t & 31;
    const int w    = t >> 5;
    const float INV = 1.0f / TEMPERATURE;

    const float rv   = g_S [(size_t)i * BSZ + t] * INV;   // logit row i
    const float cv   = g_ST[(size_t)i * BSZ + t] * INV;   // logit col i
    const float diag = g_S[(size_t)i * BSZ + i] * INV;

    // ---- block max (warp shfl + 8-entry smem hop) ----
    float rm = rv, cm = cv;
#pragma unroll
    for (int s = 16; s >= 1; s >>= 1) {
        rm = fmaxf(rm, __shfl_xor_sync(0xffffffffu, rm, s));
        cm = fmaxf(cm, __shfl_xor_sync(0xffffffffu, cm, s));
    }
    if (lane == 0) { red[0][w] = rm; red[1][w] = cm; }
    __syncthreads();
#pragma unroll
    for (int k = 0; k < 8; k++) {
        rm = fmaxf(rm, red[0][k]);
        cm = fmaxf(cm, red[1][k]);
    }
    __syncthreads();   // before red reuse

    // ---- block sum of exp ----
    float re = expf(rv - rm), ce = expf(cv - cm);
#pragma unroll
    for (int s = 16; s >= 1; s >>= 1) {
        re += __shfl_xor_sync(0xffffffffu, re, s);
        ce += __shfl_xor_sync(0xffffffffu, ce, s);
    }
    if (lane == 0) { red[0][w] = re; red[1][w] = ce; }
    __syncthreads();

    if (t == 0) {
        float rs = 0.0f, cs = 0.0f;
#pragma unroll
        for (int k = 0; k < 8; k++) { rs += red[0][k]; cs += red[1][k]; }
        g_partial[i] = (rm + logf(rs) - diag) + (cm + logf(cs) - diag);
        __threadfence();
        unsigned done = atomicAdd(&g_count, 1u);
        is_last = (done == (unsigned)(BSZ - 1)) ? 1u : 0u;
    }
    __syncthreads();

    if (is_last) {
        __threadfence();                 // make all g_partial writes visible
        float v = g_partial[t];
#pragma unroll
        for (int s = 16; s >= 1; s >>= 1) v += __shfl_xor_sync(0xffffffffu, v, s);
        if (lane == 0) bsum[w] = v;
        __syncthreads();
        if (t == 0) {
            float tot = 0.0f;
#pragma unroll
            for (int k = 0; k < 8; k++) tot += bsum[k];
            out[0] = tot * (1.0f / (2.0f * (float)BSZ));
            g_count = 0u;               // reset for next graph replay
            __threadfence();
        }
    }
}

// ---------------------------------------------------------------------------
extern "C" void kernel_launch(void* const* d_in, const int* in_sizes, int n_in,
                              void* d_out, int out_size) {
    const float* V = (const float*)d_in[0];  // v_final [256, 768]
    const float* T = (const float*)d_in[1];  // T_fused [256, 128, 768]
    float* out = (float*)d_out;

    cudaFuncSetAttribute(gemm_max_mma, cudaFuncAttributeMaxDynamicSharedMemorySize,
                         SMEM_TOTAL);

    convert_a_kernel<<<(BSZ * DDIM / 4 + 255) / 256, 256>>>(V);
    gemm_max_mma<<<dim3(4, BSZ), 128, SMEM_TOTAL>>>(T);
    lse_finalize_kernel<<<BSZ, BSZ>>>(out);
}

// round 13
// speedup vs baseline: 1.2114x; 1.1272x over previous
#include <cuda_runtime.h>
#include <cuda_fp16.h>
#include <cstdint>

#define TEMPERATURE 0.07f
constexpr int BSZ  = 256;
constexpr int MTOK = 128;
constexpr int DDIM = 768;

constexpr int KC     = 64;                 // K elements per smem stage (fp16)
constexpr int NCHUNK = DDIM / KC;          // 12
constexpr int PB     = 144;                // smem row pitch bytes (128 data + 16 pad)
constexpr int TILE_B = 128 * PB;           // 18432 bytes per tile
constexpr int STAGE_B = 2 * TILE_B;        // A, B
constexpr int SMEM_TOTAL = 2 * STAGE_B;    // 73728, double buffered -> occ 2

// Scratch device globals (no allocation allowed anywhere)
__device__ float g_S [BSZ * BSZ];          // max-sim, row-major
__device__ float g_ST[BSZ * BSZ];          // transposed copy (coalesced cols)
__device__ float g_partial[BSZ];
__device__ unsigned g_done;                // GEMM CTA arrival counter (512)
__device__ unsigned g_fin;                 // tail-slice arrival counter (4)
__device__ __align__(16) __half g_Ah[BSZ * DDIM];

// ---------------------------------------------------------------------------
__device__ __forceinline__ uint32_t smem_u32(const void* p) {
    uint32_t a;
    asm("{ .reg .u64 t; cvta.to.shared.u64 t, %1; cvt.u32.u64 %0, t; }"
        : "=r"(a) : "l"(p));
    return a;
}
__device__ __forceinline__ void cp_async16(uint32_t dst, const void* src) {
    asm volatile("cp.async.cg.shared.global [%0], [%1], 16;"
                 :: "r"(dst), "l"(src) : "memory");
}
#define CP_COMMIT() asm volatile("cp.async.commit_group;" ::: "memory")
#define CP_WAIT0()  asm volatile("cp.async.wait_group 0;" ::: "memory")

__device__ __forceinline__ void ldsm_x4(uint32_t* r, uint32_t addr) {
    asm volatile("ldmatrix.sync.aligned.m8n8.x4.shared.b16 {%0,%1,%2,%3}, [%4];"
                 : "=r"(r[0]), "=r"(r[1]), "=r"(r[2]), "=r"(r[3]) : "r"(addr));
}
__device__ __forceinline__ void mma_fp16(float* d, const uint32_t* a,
                                         const uint32_t* b) {
    asm volatile(
        "mma.sync.aligned.m16n8k16.row.col.f32.f16.f16.f32 "
        "{%0,%1,%2,%3}, {%4,%5,%6,%7}, {%8,%9}, {%0,%1,%2,%3};"
        : "+f"(d[0]), "+f"(d[1]), "+f"(d[2]), "+f"(d[3])
        : "r"(a[0]), "r"(a[1]), "r"(a[2]), "r"(a[3]), "r"(b[0]), "r"(b[1]));
}

// ---------------------------------------------------------------------------
// Kernel 0: convert V (fp32) to fp16 once; reset inter-CTA counters.
// ---------------------------------------------------------------------------
__global__ void convert_a_kernel(const float* __restrict__ V) {
    int idx = blockIdx.x * blockDim.x + threadIdx.x;   // float4 index
    if (idx == 0) { g_done = 0u; g_fin = 0u; }
    if (idx < BSZ * DDIM / 4) {
        const float4 x = *(const float4*)(V + (size_t)idx * 4);
        __half2 h01 = __floats2half2_rn(x.x, x.y);
        __half2 h23 = __floats2half2_rn(x.z, x.w);
        *(uint2*)(g_Ah + (size_t)idx * 4) =
            make_uint2(*reinterpret_cast<unsigned*>(&h01),
                       *reinterpret_cast<unsigned*>(&h23));
    }
}

// ---------------------------------------------------------------------------
// Kernel 1: single-product fp16 mma.sync GEMM + fused max over m + fused LSE
// tail. Grid (2, 256), 8 warps (4M x 2N), warp tile 32x64, occ 2.
// The last 4 CTAs to finish (arrival rank 508-511 — compute is globally done,
// so spinning is free and deadlock-impossible) each compute LSE terms for 64
// indices; the last of those does the deterministic final sum.
// ---------------------------------------------------------------------------
__global__ __launch_bounds__(256, 2)
void gemm_max_mma(const float* __restrict__ T, float* __restrict__ out) {
    extern __shared__ char smem[];
    __shared__ unsigned s_rank;
    __shared__ float s_bsum[8];
    const uint32_t sbase = smem_u32(smem);
    const int tid  = threadIdx.x;
    const int lane = tid & 31;
    const int wid  = tid >> 5;
    const int warp_m = wid & 3;
    const int warp_n = wid >> 2;

    const int i0 = blockIdx.x * 128;
    const int j  = blockIdx.y;
    const float* __restrict__ Tj = T + (size_t)j * MTOK * DDIM;

    float acc[2][8][4];
#pragma unroll
    for (int mt = 0; mt < 2; mt++)
#pragma unroll
        for (int nt = 0; nt < 8; nt++)
#pragma unroll
            for (int e = 0; e < 4; e++) acc[mt][nt][e] = 0.0f;

    // ldmatrix lane offsets (tile-relative, bytes)
    const int q   = lane >> 3;
    const int idx = lane & 7;
    const uint32_t a_off = (uint32_t)((warp_m * 32 + ((q & 1) * 8 + idx)) * PB
                                      + (q >> 1) * 16);
    const uint32_t b_off = (uint32_t)((warp_n * 64 + ((q >> 1) * 8 + idx)) * PB
                                      + (q & 1) * 16);

    float4 br[8];   // B register prefetch (fp32)

    auto fill_A = [&](uint32_t stage_u32, int k0) {
#pragma unroll
        for (int p = 0; p < 4; p++) {
            const int u   = p * 256 + tid;
            const int row = u >> 3;
            const int ku  = u & 7;
            cp_async16(stage_u32 + (uint32_t)(row * PB + ku * 16),
                       g_Ah + (size_t)(i0 + row) * DDIM + k0 + ku * 8);
        }
    };
    auto ldg_B = [&](int k0) {
#pragma unroll
        for (int p = 0; p < 8; p++) {
            const int u = p * 256 + tid;
            br[p] = *(const float4*)(Tj + (size_t)(u >> 4) * DDIM + k0 + (u & 15) * 4);
        }
    };
    auto sts_B = [&](char* stage) {
        char* sB = stage + TILE_B;
#pragma unroll
        for (int p = 0; p < 8; p++) {
            const int u   = p * 256 + tid;
            const int row = u >> 4;
            const int kq  = (u & 15) * 4;
            const float4 b = br[p];
            __half2 h01 = __floats2half2_rn(b.x, b.y);
            __half2 h23 = __floats2half2_rn(b.z, b.w);
            *(uint2*)(sB + row * PB + kq * 2) =
                make_uint2(*reinterpret_cast<unsigned*>(&h01),
                           *reinterpret_cast<unsigned*>(&h23));
        }
    };
    auto compute_step = [&](uint32_t sstage, int ks) {
        uint32_t ah[2][4], bh[4][4];
#pragma unroll
        for (int mt = 0; mt < 2; mt++)
            ldsm_x4(ah[mt], sstage + a_off + mt * 16 * PB + ks * 32);
#pragma unroll
        for (int np = 0; np < 4; np++)
            ldsm_x4(bh[np], sstage + TILE_B + b_off + np * 16 * PB + ks * 32);
#pragma unroll
        for (int np = 0; np < 4; np++)
#pragma unroll
            for (int mt = 0; mt < 2; mt++) {
                mma_fp16(acc[mt][2 * np],     ah[mt], bh[np]);
                mma_fp16(acc[mt][2 * np + 1], ah[mt], bh[np] + 2);
            }
    };

    // Prologue: chunk 0 -> stage 0.
    ldg_B(0);
    fill_A(sbase, 0);
    CP_COMMIT();
    sts_B(smem);
    CP_WAIT0();
    __syncthreads();

    for (int c = 0; c < NCHUNK; c++) {
        const int s = c & 1;
        const bool has_next = (c + 1 < NCHUNK);
        if (has_next) {
            ldg_B((c + 1) * KC);                              // LDG latency ->
            fill_A(sbase + (1 - s) * STAGE_B, (c + 1) * KC);  // hidden under
            CP_COMMIT();                                      // the MMA stream
        }
        const uint32_t sstage = sbase + s * STAGE_B;
        compute_step(sstage, 0);
        compute_step(sstage, 1);
        compute_step(sstage, 2);
        if (has_next) sts_B(smem + (1 - s) * STAGE_B);        // hidden under ks3
        compute_step(sstage, 3);
        if (has_next) CP_WAIT0();
        __syncthreads();
    }

    // Epilogue: max over the 128 m columns per i-row; write S and S^T.
    float* buf = (float*)smem;   // [128][2]
#pragma unroll
    for (int mt = 0; mt < 2; mt++) {
        float mlo = -3.402823466e+38f, mhi = -3.402823466e+38f;
#pragma unroll
        for (int nt = 0; nt < 8; nt++) {
            mlo = fmaxf(mlo, fmaxf(acc[mt][nt][0], acc[mt][nt][1]));
            mhi = fmaxf(mhi, fmaxf(acc[mt][nt][2], acc[mt][nt][3]));
        }
        mlo = fmaxf(mlo, __shfl_xor_sync(0xffffffffu, mlo, 1));
        mlo = fmaxf(mlo, __shfl_xor_sync(0xffffffffu, mlo, 2));
        mhi = fmaxf(mhi, __shfl_xor_sync(0xffffffffu, mhi, 1));
        mhi = fmaxf(mhi, __shfl_xor_sync(0xffffffffu, mhi, 2));
        if ((lane & 3) == 0) {
            const int row = warp_m * 32 + mt * 16 + (lane >> 2);
            buf[row * 2 + warp_n]       = mlo;
            buf[(row + 8) * 2 + warp_n] = mhi;
        }
    }
    __syncthreads();
    if (tid < 128) {
        const float v = fmaxf(buf[tid * 2], buf[tid * 2 + 1]);
        g_S [(size_t)(i0 + tid) * BSZ + j] = v;
        g_ST[(size_t)j * BSZ + (i0 + tid)] = v;   // coalesced
    }

    // ---- Fused LSE tail (threadfence-reduction, last-4-CTAs) --------------
    __threadfence();
    __syncthreads();
    if (tid == 0) s_rank = atomicAdd(&g_done, 1u);
    __syncthreads();
    const unsigned d = s_rank;
    if (d < 508u) return;

    const int slice = (int)(d - 508u);     // 0..3, each covers 64 indices
    if (tid == 0) { while (atomicAdd(&g_done, 0u) < 512u) {} }
    __syncthreads();
    __threadfence();

    const float INV = 1.0f / TEMPERATURE;
#pragma unroll 1
    for (int r = 0; r < 8; r++) {
        const int i = slice * 64 + wid * 8 + r;
        // Coalesced: 64 float4 per 256-float row, 2 per lane.
        const float4 r0 = __ldcg((const float4*)(g_S  + i * BSZ + 4 * lane));
        const float4 r1 = __ldcg((const float4*)(g_S  + i * BSZ + 4 * lane + 128));
        const float4 c0 = __ldcg((const float4*)(g_ST + i * BSZ + 4 * lane));
        const float4 c1 = __ldcg((const float4*)(g_ST + i * BSZ + 4 * lane + 128));
        float rm = fmaxf(fmaxf(fmaxf(r0.x, r0.y), fmaxf(r0.z, r0.w)),
                         fmaxf(fmaxf(r1.x, r1.y), fmaxf(r1.z, r1.w)));
        float cm = fmaxf(fmaxf(fmaxf(c0.x, c0.y), fmaxf(c0.z, c0.w)),
                         fmaxf(fmaxf(c1.x, c1.y), fmaxf(c1.z, c1.w)));
#pragma unroll
        for (int s = 16; s >= 1; s >>= 1) {
            rm = fmaxf(rm, __shfl_xor_sync(0xffffffffu, rm, s));
            cm = fmaxf(cm, __shfl_xor_sync(0xffffffffu, cm, s));
        }
        float rs = __expf((r0.x - rm) * INV) + __expf((r0.y - rm) * INV)
                 + __expf((r0.z - rm) * INV) + __expf((r0.w - rm) * INV)
                 + __expf((r1.x - rm) * INV) + __expf((r1.y - rm) * INV)
                 + __expf((r1.z - rm) * INV) + __expf((r1.w - rm) * INV);
        float cs = __expf((c0.x - cm) * INV) + __expf((c0.y - cm) * INV)
                 + __expf((c0.z - cm) * INV) + __expf((c0.w - cm) * INV)
                 + __expf((c1.x - cm) * INV) + __expf((c1.y - cm) * INV)
                 + __expf((c1.z - cm) * INV) + __expf((c1.w - cm) * INV);
#pragma unroll
        for (int s = 16; s >= 1; s >>= 1) {
            rs += __shfl_xor_sync(0xffffffffu, rs, s);
            cs += __shfl_xor_sync(0xffffffffu, cs, s);
        }
        if (lane == 0) {
            const float diag = __ldcg(g_S + i * BSZ + i) * INV;
            g_partial[i] = (rm * INV + __logf(rs) - diag)
                         + (cm * INV + __logf(cs) - diag);
        }
    }

    __threadfence();
    __syncthreads();
    if (tid == 0) s_rank = atomicAdd(&g_fin, 1u);
    __syncthreads();
    if (s_rank == 3u) {                    // all 4 slices complete
        __threadfence();
        float v = __ldcg(g_partial + tid);
#pragma unroll
        for (int s = 16; s >= 1; s >>= 1) v += __shfl_xor_sync(0xffffffffu, v, s);
        if (lane == 0) s_bsum[wid] = v;
        __syncthreads();
        if (tid == 0) {
            float tot = 0.0f;
#pragma unroll
            for (int k = 0; k < 8; k++) tot += s_bsum[k];
            out[0] = tot * (1.0f / (2.0f * (float)BSZ));
        }
    }
}

// ---------------------------------------------------------------------------
extern "C" void kernel_launch(void* const* d_in, const int* in_sizes, int n_in,
                              void* d_out, int out_size) {
    const float* V = (const float*)d_in[0];  // v_final [256, 768]
    const float* T = (const float*)d_in[1];  // T_fused [256, 128, 768]
    float* out = (float*)d_out;

    cudaFuncSetAttribute(gemm_max_mma, cudaFuncAttributeMaxDynamicSharedMemorySize,
                         SMEM_TOTAL);

    convert_a_kernel<<<(BSZ * DDIM / 4 + 255) / 256, 256>>>(V);
    gemm_max_mma<<<dim3(2, BSZ), 256, SMEM_TOTAL>>>(T, out);
}

// round 14
// speedup vs baseline: 1.4228x; 1.1744x over previous
#include <cuda_runtime.h>
#include <cuda_fp16.h>
#include <cstdint>

#define TEMPERATURE 0.07f
constexpr int BSZ  = 256;
constexpr int MTOK = 128;
constexpr int DDIM = 768;

constexpr int KC     = 64;                 // K elements per smem stage (fp16)
constexpr int NCHUNK = DDIM / KC;          // 12
constexpr int PB     = 144;                // smem row pitch bytes (128 data + 16 pad)
constexpr int TILE_B = 128 * PB;           // 18432 bytes per tile
constexpr int STAGE_B = 2 * TILE_B;        // A, B
constexpr int SMEM_TOTAL = 2 * STAGE_B;    // 73728, double buffered -> occ 2

// Scratch device globals (no allocation allowed anywhere)
__device__ float g_S [BSZ * BSZ];          // max-sim, row-major
__device__ float g_ST[BSZ * BSZ];          // transposed copy (coalesced cols)
__device__ float g_partial[BSZ];
__device__ unsigned g_count;               // zero-init; lse resets it each replay

// ---------------------------------------------------------------------------
__device__ __forceinline__ uint32_t smem_u32(const void* p) {
    uint32_t a;
    asm("{ .reg .u64 t; cvta.to.shared.u64 t, %1; cvt.u32.u64 %0, t; }"
        : "=r"(a) : "l"(p));
    return a;
}
__device__ __forceinline__ void ldsm_x4(uint32_t* r, uint32_t addr) {
    asm volatile("ldmatrix.sync.aligned.m8n8.x4.shared.b16 {%0,%1,%2,%3}, [%4];"
                 : "=r"(r[0]), "=r"(r[1]), "=r"(r[2]), "=r"(r[3]) : "r"(addr));
}
__device__ __forceinline__ void mma_fp16(float* d, const uint32_t* a,
                                         const uint32_t* b) {
    asm volatile(
        "mma.sync.aligned.m16n8k16.row.col.f32.f16.f16.f32 "
        "{%0,%1,%2,%3}, {%4,%5,%6,%7}, {%8,%9}, {%0,%1,%2,%3};"
        : "+f"(d[0]), "+f"(d[1]), "+f"(d[2]), "+f"(d[3])
        : "r"(a[0]), "r"(a[1]), "r"(a[2]), "r"(a[3]), "r"(b[0]), "r"(b[1]));
}

// ---------------------------------------------------------------------------
// Kernel 1: single-product fp16 mma.sync GEMM + fused max over m.
// Grid (2, 256), 8 warps (4M x 2N), warp tile 32x64, occ 2.
// BOTH A and B are loaded as fp32 and converted in-kernel; A reuses the same
// br[] registers after sts_B frees them (disjoint live ranges -> no extra
// pressure). No separate convert kernel, no cp.async.
// A fp32 (768 KB total) is re-read by 256 CTAs -> ~pure L2 hits.
// ---------------------------------------------------------------------------
__global__ __launch_bounds__(256, 2)
void gemm_max_mma(const float* __restrict__ V, const float* __restrict__ T) {
    extern __shared__ char smem[];
    const uint32_t sbase = smem_u32(smem);
    const int tid  = threadIdx.x;
    const int lane = tid & 31;
    const int wid  = tid >> 5;
    const int warp_m = wid & 3;
    const int warp_n = wid >> 2;

    const int i0 = blockIdx.x * 128;
    const int j  = blockIdx.y;
    const float* __restrict__ Tj = T + (size_t)j * MTOK * DDIM;
    const float* __restrict__ Vi = V + (size_t)i0 * DDIM;

    float acc[2][8][4];
#pragma unroll
    for (int mt = 0; mt < 2; mt++)
#pragma unroll
        for (int nt = 0; nt < 8; nt++)
#pragma unroll
            for (int e = 0; e < 4; e++) acc[mt][nt][e] = 0.0f;

    // ldmatrix lane offsets (tile-relative, bytes)
    const int q   = lane >> 3;
    const int idx = lane & 7;
    const uint32_t a_off = (uint32_t)((warp_m * 32 + ((q & 1) * 8 + idx)) * PB
                                      + (q >> 1) * 16);
    const uint32_t b_off = (uint32_t)((warp_n * 64 + ((q >> 1) * 8 + idx)) * PB
                                      + (q & 1) * 16);

    float4 br[8];   // shared prefetch buffer: B, then A (disjoint live ranges)

    // 8 float4 per thread covering 128 rows x 64 k fp32 of matrix `src`.
    auto ldg_tile = [&](const float* __restrict__ src, int k0) {
#pragma unroll
        for (int p = 0; p < 8; p++) {
            const int u = p * 256 + tid;
            br[p] = *(const float4*)(src + (size_t)(u >> 4) * DDIM + k0 + (u & 15) * 4);
        }
    };
    // Convert br[] fp32 -> fp16 and store into tile at `base` within stage.
    auto sts_tile = [&](char* stage, int base) {
        char* sD = stage + base;
#pragma unroll
        for (int p = 0; p < 8; p++) {
            const int u   = p * 256 + tid;
            const int row = u >> 4;
            const int kq  = (u & 15) * 4;
            const float4 b = br[p];
            __half2 h01 = __floats2half2_rn(b.x, b.y);
            __half2 h23 = __floats2half2_rn(b.z, b.w);
            *(uint2*)(sD + row * PB + kq * 2) =
                make_uint2(*reinterpret_cast<unsigned*>(&h01),
                           *reinterpret_cast<unsigned*>(&h23));
        }
    };
    auto compute_step = [&](uint32_t sstage, int ks) {
        uint32_t ah[2][4], bh[4][4];
#pragma unroll
        for (int mt = 0; mt < 2; mt++)
            ldsm_x4(ah[mt], sstage + a_off + mt * 16 * PB + ks * 32);
#pragma unroll
        for (int np = 0; np < 4; np++)
            ldsm_x4(bh[np], sstage + TILE_B + b_off + np * 16 * PB + ks * 32);
#pragma unroll
        for (int np = 0; np < 4; np++)
#pragma unroll
            for (int mt = 0; mt < 2; mt++) {
                mma_fp16(acc[mt][2 * np],     ah[mt], bh[np]);
                mma_fp16(acc[mt][2 * np + 1], ah[mt], bh[np] + 2);
            }
    };

    // Prologue: chunk 0 -> stage 0 (A then B, sequential br reuse).
    ldg_tile(Vi, 0);
    sts_tile(smem, 0);           // A tile at stage offset 0
    ldg_tile(Tj, 0);
    sts_tile(smem, TILE_B);      // B tile at stage offset TILE_B
    __syncthreads();

    for (int c = 0; c < NCHUNK; c++) {
        const int s = c & 1;
        const bool has_next = (c + 1 < NCHUNK);
        const int  knext = (c + 1) * KC;
        char* other = smem + (1 - s) * STAGE_B;
        if (has_next) ldg_tile(Tj, knext);                 // B LDG latency ->
        const uint32_t sstage = sbase + s * STAGE_B;       // hidden under MMAs
        compute_step(sstage, 0);
        compute_step(sstage, 1);
        compute_step(sstage, 2);
        if (has_next) {
            sts_tile(other, TILE_B);                       // B regs -> smem
            ldg_tile(Vi, knext);                           // A LDG (L2-hot),
        }                                                  // br reused
        compute_step(sstage, 3);
        if (has_next) sts_tile(other, 0);                  // A regs -> smem
        __syncthreads();
    }

    // Epilogue: max over the 128 m columns per i-row; write S and S^T.
    float* buf = (float*)smem;   // [128][2]
#pragma unroll
    for (int mt = 0; mt < 2; mt++) {
        float mlo = -3.402823466e+38f, mhi = -3.402823466e+38f;
#pragma unroll
        for (int nt = 0; nt < 8; nt++) {
            mlo = fmaxf(mlo, fmaxf(acc[mt][nt][0], acc[mt][nt][1]));
            mhi = fmaxf(mhi, fmaxf(acc[mt][nt][2], acc[mt][nt][3]));
        }
        mlo = fmaxf(mlo, __shfl_xor_sync(0xffffffffu, mlo, 1));
        mlo = fmaxf(mlo, __shfl_xor_sync(0xffffffffu, mlo, 2));
        mhi = fmaxf(mhi, __shfl_xor_sync(0xffffffffu, mhi, 1));
        mhi = fmaxf(mhi, __shfl_xor_sync(0xffffffffu, mhi, 2));
        if ((lane & 3) == 0) {
            const int row = warp_m * 32 + mt * 16 + (lane >> 2);
            buf[row * 2 + warp_n]       = mlo;
            buf[(row + 8) * 2 + warp_n] = mhi;
        }
    }
    __syncthreads();
    if (tid < 128) {
        const float v = fmaxf(buf[tid * 2], buf[tid * 2 + 1]);
        g_S [(size_t)(i0 + tid) * BSZ + j] = v;
        g_ST[(size_t)j * BSZ + (i0 + tid)] = v;   // coalesced
    }
}

// ---------------------------------------------------------------------------
// Kernel 2: per-index LSE terms via shfl reductions (coalesced reads from
// g_S and g_ST, MUFU exp); last block does the deterministic final sum and
// resets the counter for the next graph replay.
// ---------------------------------------------------------------------------
__global__ void lse_finalize_kernel(float* __restrict__ out) {
    __shared__ float red[2][8];
    __shared__ float bsum[8];
    __shared__ unsigned is_last;
    const int i    = blockIdx.x;
    const int t    = threadIdx.x;
    const int lane = t & 31;
    const int w    = t >> 5;
    const float INV = 1.0f / TEMPERATURE;

    const float rv   = g_S [(size_t)i * BSZ + t] * INV;   // logit row i
    const float cv   = g_ST[(size_t)i * BSZ + t] * INV;   // logit col i
    const float diag = g_S[(size_t)i * BSZ + i] * INV;

    // ---- block max (warp shfl + 8-entry smem hop) ----
    float rm = rv, cm = cv;
#pragma unroll
    for (int s = 16; s >= 1; s >>= 1) {
        rm = fmaxf(rm, __shfl_xor_sync(0xffffffffu, rm, s));
        cm = fmaxf(cm, __shfl_xor_sync(0xffffffffu, cm, s));
    }
    if (lane == 0) { red[0][w] = rm; red[1][w] = cm; }
    __syncthreads();
#pragma unroll
    for (int k = 0; k < 8; k++) {
        rm = fmaxf(rm, red[0][k]);
        cm = fmaxf(cm, red[1][k]);
    }
    __syncthreads();   // before red reuse

    // ---- block sum of exp (MUFU) ----
    float re = __expf(rv - rm), ce = __expf(cv - cm);
#pragma unroll
    for (int s = 16; s >= 1; s >>= 1) {
        re += __shfl_xor_sync(0xffffffffu, re, s);
        ce += __shfl_xor_sync(0xffffffffu, ce, s);
    }
    if (lane == 0) { red[0][w] = re; red[1][w] = ce; }
    __syncthreads();

    if (t == 0) {
        float rs = 0.0f, cs = 0.0f;
#pragma unroll
        for (int k = 0; k < 8; k++) { rs += red[0][k]; cs += red[1][k]; }
        g_partial[i] = (rm + logf(rs) - diag) + (cm + logf(cs) - diag);
        __threadfence();
        unsigned done = atomicAdd(&g_count, 1u);
        is_last = (done == (unsigned)(BSZ - 1)) ? 1u : 0u;
    }
    __syncthreads();

    if (is_last) {
        __threadfence();                 // make all g_partial writes visible
        float v = g_partial[t];
#pragma unroll
        for (int s = 16; s >= 1; s >>= 1) v += __shfl_xor_sync(0xffffffffu, v, s);
        if (lane == 0) bsum[w] = v;
        __syncthreads();
        if (t == 0) {
            float tot = 0.0f;
#pragma unroll
            for (int k = 0; k < 8; k++) tot += bsum[k];
            out[0] = tot * (1.0f / (2.0f * (float)BSZ));
            g_count = 0u;               // reset for next graph replay
            __threadfence();
        }
    }
}

// ---------------------------------------------------------------------------
extern "C" void kernel_launch(void* const* d_in, const int* in_sizes, int n_in,
                              void* d_out, int out_size) {
    const float* V = (const float*)d_in[0];  // v_final [256, 768]
    const float* T = (const float*)d_in[1];  // T_fused [256, 128, 768]
    float* out = (float*)d_out;

    cudaFuncSetAttribute(gemm_max_mma, cudaFuncAttributeMaxDynamicSharedMemorySize,
                         SMEM_TOTAL);

    gemm_max_mma<<<dim3(2, BSZ), 256, SMEM_TOTAL>>>(V, T);
    lse_finalize_kernel<<<BSZ, BSZ>>>(out);
}

// round 15
// speedup vs baseline: 1.4236x; 1.0006x over previous
#include <cuda_runtime.h>
#include <cuda_fp16.h>
#include <cstdint>

#define TEMPERATURE 0.07f
constexpr int BSZ  = 256;
constexpr int MTOK = 128;
constexpr int DDIM = 768;

constexpr int KC     = 64;                 // K elements per smem stage (fp16)
constexpr int NCHUNK = DDIM / KC;          // 12
constexpr int PB     = 144;                // smem row pitch bytes (128 data + 16 pad)
constexpr int TILE_B = 128 * PB;           // 18432 bytes per tile
constexpr int STAGE_B = 2 * TILE_B;        // A, B
constexpr int SMEM_TOTAL = 2 * STAGE_B;    // 73728, double buffered -> occ 2

// Scratch device globals (no allocation allowed anywhere)
__device__ float g_S [BSZ * BSZ];          // max-sim, row-major
__device__ float g_ST[BSZ * BSZ];          // transposed copy (coalesced cols)
__device__ float g_partial[BSZ];
__device__ unsigned g_count;               // zero-init; lse resets it each replay

// ---------------------------------------------------------------------------
__device__ __forceinline__ uint32_t smem_u32(const void* p) {
    uint32_t a;
    asm("{ .reg .u64 t; cvta.to.shared.u64 t, %1; cvt.u32.u64 %0, t; }"
        : "=r"(a) : "l"(p));
    return a;
}
__device__ __forceinline__ void ldsm_x4(uint32_t* r, uint32_t addr) {
    asm volatile("ldmatrix.sync.aligned.m8n8.x4.shared.b16 {%0,%1,%2,%3}, [%4];"
                 : "=r"(r[0]), "=r"(r[1]), "=r"(r[2]), "=r"(r[3]) : "r"(addr));
}
__device__ __forceinline__ void mma_fp16(float* d, const uint32_t* a,
                                         const uint32_t* b) {
    asm volatile(
        "mma.sync.aligned.m16n8k16.row.col.f32.f16.f16.f32 "
        "{%0,%1,%2,%3}, {%4,%5,%6,%7}, {%8,%9}, {%0,%1,%2,%3};"
        : "+f"(d[0]), "+f"(d[1]), "+f"(d[2]), "+f"(d[3])
        : "r"(a[0]), "r"(a[1]), "r"(a[2]), "r"(a[3]), "r"(b[0]), "r"(b[1]));
}

// ---------------------------------------------------------------------------
// Kernel 1: single-product fp16 mma.sync GEMM + fused max over m.
// Grid (2, 256), 8 warps (4M x 2N), warp tile 32x64, occ 2.
// BOTH A and B loaded as fp32 and converted in-kernel; A reuses the br[]
// registers after sts(B) frees them (disjoint live ranges, no extra pressure).
// ---------------------------------------------------------------------------
__global__ __launch_bounds__(256, 2)
void gemm_max_mma(const float* __restrict__ V, const float* __restrict__ T) {
    extern __shared__ char smem[];
    const uint32_t sbase = smem_u32(smem);
    const int tid  = threadIdx.x;
    const int lane = tid & 31;
    const int wid  = tid >> 5;
    const int warp_m = wid & 3;
    const int warp_n = wid >> 2;

    const int i0 = blockIdx.x * 128;
    const int j  = blockIdx.y;
    const float* __restrict__ Tj = T + (size_t)j * MTOK * DDIM;
    const float* __restrict__ Vi = V + (size_t)i0 * DDIM;

    float acc[2][8][4];
#pragma unroll
    for (int mt = 0; mt < 2; mt++)
#pragma unroll
        for (int nt = 0; nt < 8; nt++)
#pragma unroll
            for (int e = 0; e < 4; e++) acc[mt][nt][e] = 0.0f;

    // ldmatrix lane offsets (tile-relative, bytes)
    const int q   = lane >> 3;
    const int idx = lane & 7;
    const uint32_t a_off = (uint32_t)((warp_m * 32 + ((q & 1) * 8 + idx)) * PB
                                      + (q >> 1) * 16);
    const uint32_t b_off = (uint32_t)((warp_n * 64 + ((q >> 1) * 8 + idx)) * PB
                                      + (q & 1) * 16);

    float4 br[8];   // shared prefetch buffer: B, then A (disjoint live ranges)

    auto ldg_tile = [&](const float* __restrict__ src, int k0) {
#pragma unroll
        for (int p = 0; p < 8; p++) {
            const int u = p * 256 + tid;
            br[p] = *(const float4*)(src + (size_t)(u >> 4) * DDIM + k0 + (u & 15) * 4);
        }
    };
    auto sts_tile = [&](char* stage, int base) {
        char* sD = stage + base;
#pragma unroll
        for (int p = 0; p < 8; p++) {
            const int u   = p * 256 + tid;
            const int row = u >> 4;
            const int kq  = (u & 15) * 4;
            const float4 b = br[p];
            __half2 h01 = __floats2half2_rn(b.x, b.y);
            __half2 h23 = __floats2half2_rn(b.z, b.w);
            *(uint2*)(sD + row * PB + kq * 2) =
                make_uint2(*reinterpret_cast<unsigned*>(&h01),
                           *reinterpret_cast<unsigned*>(&h23));
        }
    };
    auto compute_step = [&](uint32_t sstage, int ks) {
        uint32_t ah[2][4], bh[4][4];
#pragma unroll
        for (int mt = 0; mt < 2; mt++)
            ldsm_x4(ah[mt], sstage + a_off + mt * 16 * PB + ks * 32);
#pragma unroll
        for (int np = 0; np < 4; np++)
            ldsm_x4(bh[np], sstage + TILE_B + b_off + np * 16 * PB + ks * 32);
#pragma unroll
        for (int np = 0; np < 4; np++)
#pragma unroll
            for (int mt = 0; mt < 2; mt++) {
                mma_fp16(acc[mt][2 * np],     ah[mt], bh[np]);
                mma_fp16(acc[mt][2 * np + 1], ah[mt], bh[np] + 2);
            }
    };

    // Prologue: chunk 0 -> stage 0 (A then B, sequential br reuse).
    ldg_tile(Vi, 0);
    sts_tile(smem, 0);           // A tile at stage offset 0
    ldg_tile(Tj, 0);
    sts_tile(smem, TILE_B);      // B tile at stage offset TILE_B
    __syncthreads();

    for (int c = 0; c < NCHUNK; c++) {
        const int s = c & 1;
        const bool has_next = (c + 1 < NCHUNK);
        const int  knext = (c + 1) * KC;
        char* other = smem + (1 - s) * STAGE_B;
        if (has_next) ldg_tile(Tj, knext);                 // B LDG latency ->
        const uint32_t sstage = sbase + s * STAGE_B;       // hidden under MMAs
        compute_step(sstage, 0);
        compute_step(sstage, 1);
        compute_step(sstage, 2);
        if (has_next) {
            sts_tile(other, TILE_B);                       // B regs -> smem
            ldg_tile(Vi, knext);                           // A LDG (L2-hot)
        }
        compute_step(sstage, 3);
        if (has_next) sts_tile(other, 0);                  // A regs -> smem
        __syncthreads();
    }

    // Epilogue: max over the 128 m columns per i-row; write S and S^T.
    float* buf = (float*)smem;   // [128][2]
#pragma unroll
    for (int mt = 0; mt < 2; mt++) {
        float mlo = -3.402823466e+38f, mhi = -3.402823466e+38f;
#pragma unroll
        for (int nt = 0; nt < 8; nt++) {
            mlo = fmaxf(mlo, fmaxf(acc[mt][nt][0], acc[mt][nt][1]));
            mhi = fmaxf(mhi, fmaxf(acc[mt][nt][2], acc[mt][nt][3]));
        }
        mlo = fmaxf(mlo, __shfl_xor_sync(0xffffffffu, mlo, 1));
        mlo = fmaxf(mlo, __shfl_xor_sync(0xffffffffu, mlo, 2));
        mhi = fmaxf(mhi, __shfl_xor_sync(0xffffffffu, mhi, 1));
        mhi = fmaxf(mhi, __shfl_xor_sync(0xffffffffu, mhi, 2));
        if ((lane & 3) == 0) {
            const int row = warp_m * 32 + mt * 16 + (lane >> 2);
            buf[row * 2 + warp_n]       = mlo;
            buf[(row + 8) * 2 + warp_n] = mhi;
        }
    }
    __syncthreads();
    if (tid < 128) {
        const float v = fmaxf(buf[tid * 2], buf[tid * 2 + 1]);
        g_S [(size_t)(i0 + tid) * BSZ + j] = v;
        g_ST[(size_t)j * BSZ + (i0 + tid)] = v;   // coalesced
    }
}

// ---------------------------------------------------------------------------
// Kernel 2: warp-per-row LSE (no block barriers in the hot path).
// Grid 32 x 256 threads: warp w of block b owns index i = b*8 + w. Each lane
// reads 2 float4 from the S row and 2 from the ST row (fully coalesced),
// reduces max and exp-sum purely in shfl. Last block (threadfence-reduction)
// does the deterministic fixed-order final sum and resets the counter.
// ---------------------------------------------------------------------------
__global__ __launch_bounds__(256)
void lse_finalize_kernel(float* __restrict__ out) {
    __shared__ float bsum[8];
    __shared__ unsigned is_last;
    const int t    = threadIdx.x;
    const int lane = t & 31;
    const int w    = t >> 5;
    const int i    = blockIdx.x * 8 + w;
    const float INV = 1.0f / TEMPERATURE;

    const float4 r0 = *(const float4*)(g_S  + (size_t)i * BSZ + 4 * lane);
    const float4 r1 = *(const float4*)(g_S  + (size_t)i * BSZ + 128 + 4 * lane);
    const float4 c0 = *(const float4*)(g_ST + (size_t)i * BSZ + 4 * lane);
    const float4 c1 = *(const float4*)(g_ST + (size_t)i * BSZ + 128 + 4 * lane);

    float rm = fmaxf(fmaxf(fmaxf(r0.x, r0.y), fmaxf(r0.z, r0.w)),
                     fmaxf(fmaxf(r1.x, r1.y), fmaxf(r1.z, r1.w)));
    float cm = fmaxf(fmaxf(fmaxf(c0.x, c0.y), fmaxf(c0.z, c0.w)),
                     fmaxf(fmaxf(c1.x, c1.y), fmaxf(c1.z, c1.w)));
#pragma unroll
    for (int s = 16; s >= 1; s >>= 1) {
        rm = fmaxf(rm, __shfl_xor_sync(0xffffffffu, rm, s));
        cm = fmaxf(cm, __shfl_xor_sync(0xffffffffu, cm, s));
    }

    float rs = __expf((r0.x - rm) * INV) + __expf((r0.y - rm) * INV)
             + __expf((r0.z - rm) * INV) + __expf((r0.w - rm) * INV)
             + __expf((r1.x - rm) * INV) + __expf((r1.y - rm) * INV)
             + __expf((r1.z - rm) * INV) + __expf((r1.w - rm) * INV);
    float cs = __expf((c0.x - cm) * INV) + __expf((c0.y - cm) * INV)
             + __expf((c0.z - cm) * INV) + __expf((c0.w - cm) * INV)
             + __expf((c1.x - cm) * INV) + __expf((c1.y - cm) * INV)
             + __expf((c1.z - cm) * INV) + __expf((c1.w - cm) * INV);
#pragma unroll
    for (int s = 16; s >= 1; s >>= 1) {
        rs += __shfl_xor_sync(0xffffffffu, rs, s);
        cs += __shfl_xor_sync(0xffffffffu, cs, s);
    }

    if (lane == 0) {
        const float diag = g_S[(size_t)i * BSZ + i] * INV;
        g_partial[i] = (rm * INV + logf(rs) - diag)
                     + (cm * INV + logf(cs) - diag);
    }

    // ---- threadfence-reduction: last of 32 blocks does the final sum ------
    __threadfence();
    __syncthreads();
    if (t == 0) {
        unsigned done = atomicAdd(&g_count, 1u);
        is_last = (done == 31u) ? 1u : 0u;
    }
    __syncthreads();

    if (is_last) {
        __threadfence();                 // make all g_partial writes visible
        float v = g_partial[t];
#pragma unroll
        for (int s = 16; s >= 1; s >>= 1) v += __shfl_xor_sync(0xffffffffu, v, s);
        if (lane == 0) bsum[w] = v;
        __syncthreads();
        if (t == 0) {
            float tot = 0.0f;
#pragma unroll
            for (int k = 0; k < 8; k++) tot += bsum[k];
            out[0] = tot * (1.0f / (2.0f * (float)BSZ));
            g_count = 0u;               // reset for next graph replay
            __threadfence();
        }
    }
}

// ---------------------------------------------------------------------------
extern "C" void kernel_launch(void* const* d_in, const int* in_sizes, int n_in,
                              void* d_out, int out_size) {
    const float* V = (const float*)d_in[0];  // v_final [256, 768]
    const float* T = (const float*)d_in[1];  // T_fused [256, 128, 768]
    float* out = (float*)d_out;

    cudaFuncSetAttribute(gemm_max_mma, cudaFuncAttributeMaxDynamicSharedMemorySize,
                         SMEM_TOTAL);

    gemm_max_mma<<<dim3(2, BSZ), 256, SMEM_TOTAL>>>(V, T);
    lse_finalize_kernel<<<32, 256>>>(out);
}